// round 3
// baseline (speedup 1.0000x reference)
#include <cuda_runtime.h>
#include <cuda_bf16.h>
#include <math.h>
#include <stdint.h>

// ---------------- scratch (device globals; no allocs allowed) ----------------
__device__ float g_z[512 * 448];           // z padded to 448 cols (cols 432..447 = 0)
__device__ float g_part[9 * 512 * 512];    // split-K partials
__device__ float g_h1[512 * 512];          // relu(inter@pw0+pb0)

// round fp32 -> tf32 (nearest) kept in a float container
__device__ __forceinline__ float rtf(float x) {
    uint32_t u;
    asm("cvt.rna.tf32.f32 %0, %1;" : "=r"(u) : "f"(x));
    return __uint_as_float(u);
}

// ---------------- kernel 1: dense MLP (4 batch rows / block) ----------------
__global__ void dense_mlp_kernel(const float* __restrict__ x,
                                 const float* __restrict__ dw0, const float* __restrict__ db0,
                                 const float* __restrict__ dw1, const float* __restrict__ db1,
                                 const float* __restrict__ dw2, const float* __restrict__ db2,
                                 const float* __restrict__ dw3, const float* __restrict__ db3) {
    __shared__ float xs[4][13];
    __shared__ float h0[4][512];
    __shared__ float h1[4][256];
    __shared__ float h2[4][64];
    const int r0 = blockIdx.x * 4;
    const int tid = threadIdx.x;

    if (tid < 52) xs[tid / 13][tid % 13] = x[(r0 + tid / 13) * 13 + tid % 13];
    __syncthreads();

    // layer 0: 13 -> 512
    #pragma unroll
    for (int jj = 0; jj < 2; jj++) {
        int j = tid + jj * 256;
        float a[4];
        float b = db0[j];
        #pragma unroll
        for (int r = 0; r < 4; r++) a[r] = b;
        #pragma unroll
        for (int i = 0; i < 13; i++) {
            float w = dw0[i * 512 + j];
            #pragma unroll
            for (int r = 0; r < 4; r++) a[r] += xs[r][i] * w;
        }
        #pragma unroll
        for (int r = 0; r < 4; r++) h0[r][j] = fmaxf(a[r], 0.f);
    }
    __syncthreads();

    // layer 1: 512 -> 256
    {
        float a[4];
        float b = db1[tid];
        #pragma unroll
        for (int r = 0; r < 4; r++) a[r] = b;
        #pragma unroll 8
        for (int i = 0; i < 512; i++) {
            float w = dw1[i * 256 + tid];
            #pragma unroll
            for (int r = 0; r < 4; r++) a[r] += h0[r][i] * w;
        }
        #pragma unroll
        for (int r = 0; r < 4; r++) h1[r][tid] = fmaxf(a[r], 0.f);
    }
    __syncthreads();

    // layer 2: 256 -> 64
    if (tid < 64) {
        float a[4];
        float b = db2[tid];
        #pragma unroll
        for (int r = 0; r < 4; r++) a[r] = b;
        #pragma unroll 8
        for (int i = 0; i < 256; i++) {
            float w = dw2[i * 64 + tid];
            #pragma unroll
            for (int r = 0; r < 4; r++) a[r] += h1[r][i] * w;
        }
        #pragma unroll
        for (int r = 0; r < 4; r++) h2[r][tid] = fmaxf(a[r], 0.f);
    }
    __syncthreads();

    // layer 3: 64 -> 16 (linear) -> z[:,0:16]
    if (tid < 16) {
        float a[4];
        float b = db3[tid];
        #pragma unroll
        for (int r = 0; r < 4; r++) a[r] = b;
        #pragma unroll
        for (int i = 0; i < 64; i++) {
            float w = dw3[i * 16 + tid];
            #pragma unroll
            for (int r = 0; r < 4; r++) a[r] += h2[r][i] * w;
        }
        #pragma unroll
        for (int r = 0; r < 4; r++) g_z[(size_t)(r0 + r) * 448 + tid] = a[r];
    }
    // zero padding columns 432..447
    if (tid >= 64 && tid < 128) {
        int u = tid - 64;
        g_z[(size_t)(r0 + u / 16) * 448 + 432 + (u % 16)] = 0.f;
    }
}

// ---------------- kernel 2: embedding gather -> z[:,16:432] ----------------
__global__ void embed_kernel(const void* __restrict__ sp, const float* __restrict__ emb) {
    int t = blockIdx.x * blockDim.x + threadIdx.x;
    if (t >= 512 * 26) return;
    const int* si = (const int*)sp;
    // int64 vs int32 autodetect: values < 1e5, so int64 high words are 0.
    bool is64 = (si[1] == 0 && si[3] == 0 && si[5] == 0);
    long long v = is64 ? ((const long long*)sp)[t] : (long long)si[t];
    int id = (int)((v + 1) % 100000);
    int b = t / 26, f = t - b * 26;
    const float4* src = (const float4*)(emb + ((size_t)f * 100000 + id) * 16);
    float4* dst = (float4*)(g_z + (size_t)b * 448 + 16 + f * 16);
    dst[0] = src[0]; dst[1] = src[1]; dst[2] = src[2]; dst[3] = src[3];
}

// ---------------- kernel 3: interaction GEMM (tf32 mma.sync), split-K ------
// C[512,512] = A[512,K] @ W0[K,512], A[b, p*432+q] = z[b,p]*z[b,q]
// per CTA: 128x128 tile, 48 p's (one split), q padded to 448 (14 chunks of 32)
#define GEMM_SMEM_FLOATS (128 * 33 + 128 * 49 + 2 * 32 * 132)

__global__ __launch_bounds__(256) void inter_gemm_kernel(const float* __restrict__ W0) {
    extern __shared__ float sm[];
    float* zq_s = sm;                        // [128][33]
    float* zp_s = sm + 128 * 33;             // [128][49]
    float* B_sm = sm + 128 * 33 + 128 * 49;  // [2][32][132]

    const int tid = threadIdx.x;
    const int warp = tid >> 5, lane = tid & 31;
    const int g = lane >> 2, c = lane & 3;             // mma group / thread-in-group
    const int n0 = blockIdx.x * 128;
    const int m0 = blockIdx.y * 128;
    const int p0 = blockIdx.z * 48;
    const int wm0 = (warp >> 2) * 64, wn0 = (warp & 3) * 32;
    const int bk = tid >> 3;        // B stage: row (k) 0..31
    const int c8 = tid & 7;         // B stage: float4 col group

    // stage zp (this split's 48 p-columns of z), pre-rounded to tf32
    for (int i = tid; i < 128 * 48; i += 256) {
        int b = i / 48, j = i - b * 48;
        zp_s[b * 49 + j] = rtf(g_z[(size_t)(m0 + b) * 448 + p0 + j]);
    }

    float acc[4][4][4];
    #pragma unroll
    for (int mi = 0; mi < 4; mi++)
        #pragma unroll
        for (int nj = 0; nj < 4; nj++)
            #pragma unroll
            for (int k = 0; k < 4; k++) acc[mi][nj][k] = 0.f;

    float4 breg[4];
#define LOAD_B(IT) {                                                        \
        int qq = (IT) / 48, pp = (IT) - qq * 48;                            \
        long long gk = (long long)(p0 + pp) * 432 + qq * 32 + bk;           \
        if (gk > 186623LL) gk = 186623LL;  /* padded q>=432: A==0 there */  \
        const float4* s4 = (const float4*)(W0 + gk * 512 + n0);             \
        breg[0] = s4[c8]; breg[1] = s4[c8 + 8];                             \
        breg[2] = s4[c8 + 16]; breg[3] = s4[c8 + 24]; }

    LOAD_B(0);
    float zq_r[8][8];
    float zp_r[8];

    for (int it = 0; it < 672; ++it) {             // 14 q-chunks * 48 p
        int qc = it / 48, pi = it - qc * 48;
        if (pi == 0) {
            __syncthreads();
            for (int i = tid; i < 128 * 32; i += 256) {
                int b = i >> 5, kk = i & 31;
                zq_s[b * 33 + kk] = rtf(g_z[(size_t)(m0 + b) * 448 + qc * 32 + kk]);
            }
            __syncthreads();
            #pragma unroll
            for (int j = 0; j < 8; j++)
                #pragma unroll
                for (int u = 0; u < 8; u++)
                    zq_r[j][u] = zq_s[(wm0 + g + 8 * j) * 33 + c + 4 * u];
        }
        // commit prefetched B tile to smem (rounded to tf32)
        float* bb = B_sm + (it & 1) * (32 * 132);
        #pragma unroll
        for (int i = 0; i < 4; i++) {
            float4 v;
            v.x = rtf(breg[i].x); v.y = rtf(breg[i].y);
            v.z = rtf(breg[i].z); v.w = rtf(breg[i].w);
            *(float4*)(bb + bk * 132 + (c8 + 8 * i) * 4) = v;
        }
        __syncthreads();
        if (it + 1 < 672) LOAD_B(it + 1);  // prefetch next; latency hidden by MMA

        #pragma unroll
        for (int j = 0; j < 8; j++) zp_r[j] = zp_s[(wm0 + g + 8 * j) * 49 + pi];

        #pragma unroll
        for (int ks = 0; ks < 4; ks++) {
            uint32_t bu[4][2];
            #pragma unroll
            for (int nj = 0; nj < 4; nj++) {
                bu[nj][0] = __float_as_uint(bb[(ks * 8 + c)     * 132 + wn0 + nj * 8 + g]);
                bu[nj][1] = __float_as_uint(bb[(ks * 8 + c + 4) * 132 + wn0 + nj * 8 + g]);
            }
            #pragma unroll
            for (int mi = 0; mi < 4; mi++) {
                uint32_t a0 = __float_as_uint(zp_r[2 * mi]     * zq_r[2 * mi][2 * ks]);
                uint32_t a1 = __float_as_uint(zp_r[2 * mi + 1] * zq_r[2 * mi + 1][2 * ks]);
                uint32_t a2 = __float_as_uint(zp_r[2 * mi]     * zq_r[2 * mi][2 * ks + 1]);
                uint32_t a3 = __float_as_uint(zp_r[2 * mi + 1] * zq_r[2 * mi + 1][2 * ks + 1]);
                #pragma unroll
                for (int nj = 0; nj < 4; nj++) {
                    asm volatile(
                        "mma.sync.aligned.m16n8k8.row.col.f32.tf32.tf32.f32 "
                        "{%0,%1,%2,%3},{%4,%5,%6,%7},{%8,%9},{%0,%1,%2,%3};"
                        : "+f"(acc[mi][nj][0]), "+f"(acc[mi][nj][1]),
                          "+f"(acc[mi][nj][2]), "+f"(acc[mi][nj][3])
                        : "r"(a0), "r"(a1), "r"(a2), "r"(a3),
                          "r"(bu[nj][0]), "r"(bu[nj][1]));
                }
            }
        }
    }

    // epilogue: write split partials
    #pragma unroll
    for (int mi = 0; mi < 4; mi++)
        #pragma unroll
        for (int nj = 0; nj < 4; nj++) {
            int row = m0 + wm0 + 16 * mi + g;
            int col = n0 + wn0 + 8 * nj + 2 * c;
            float* d0 = g_part + ((size_t)blockIdx.z * 512 + row) * 512 + col;
            float* d1 = g_part + ((size_t)blockIdx.z * 512 + row + 8) * 512 + col;
            *(float2*)d0 = make_float2(acc[mi][nj][0], acc[mi][nj][1]);
            *(float2*)d1 = make_float2(acc[mi][nj][2], acc[mi][nj][3]);
        }
}
#undef LOAD_B

// ---------------- kernel 4: reduce split-K partials + bias + relu ----------
__global__ void reduce_relu_kernel(const float* __restrict__ pb0) {
    int b = blockIdx.x;
    for (int j = threadIdx.x; j < 512; j += 256) {
        float s = pb0[j];
        #pragma unroll
        for (int sp = 0; sp < 9; sp++)
            s += g_part[((size_t)sp * 512 + b) * 512 + j];
        g_h1[(size_t)b * 512 + j] = fmaxf(s, 0.f);
    }
}

// ---------------- kernel 5: prediction MLP + sigmoid -----------------------
__global__ void pred_kernel(const float* __restrict__ pw1, const float* __restrict__ pb1,
                            const float* __restrict__ pw2, const float* __restrict__ pb2,
                            float* __restrict__ out) {
    __shared__ float h1s[4][512];
    __shared__ float h2s[4][256];
    __shared__ float red[4][8];
    const int r0 = blockIdx.x * 4;
    const int tid = threadIdx.x;

    for (int i = tid; i < 2048; i += 256)
        h1s[i >> 9][i & 511] = g_h1[(size_t)(r0 + (i >> 9)) * 512 + (i & 511)];
    __syncthreads();

    {
        float a[4];
        float b = pb1[tid];
        #pragma unroll
        for (int r = 0; r < 4; r++) a[r] = b;
        #pragma unroll 8
        for (int i = 0; i < 512; i++) {
            float w = pw1[i * 256 + tid];
            #pragma unroll
            for (int r = 0; r < 4; r++) a[r] += h1s[r][i] * w;
        }
        #pragma unroll
        for (int r = 0; r < 4; r++) h2s[r][tid] = fmaxf(a[r], 0.f);
    }
    __syncthreads();

    float w2 = pw2[tid];
    int lane = tid & 31, wp = tid >> 5;
    #pragma unroll
    for (int r = 0; r < 4; r++) {
        float v = h2s[r][tid] * w2;
        #pragma unroll
        for (int o = 16; o; o >>= 1) v += __shfl_xor_sync(0xffffffffu, v, o);
        if (lane == 0) red[r][wp] = v;
    }
    __syncthreads();
    if (tid < 4) {
        float s = pb2[0];
        #pragma unroll
        for (int w = 0; w < 8; w++) s += red[tid][w];
        out[r0 + tid] = 1.f / (1.f + expf(-s));
    }
}

// ---------------- launch ----------------------------------------------------
extern "C" void kernel_launch(void* const* d_in, const int* in_sizes, int n_in,
                              void* d_out, int out_size) {
    const float* x   = (const float*)d_in[0];
    const void*  sp  = d_in[1];
    const float* emb = (const float*)d_in[2];
    const float* dw0 = (const float*)d_in[3];
    const float* db0 = (const float*)d_in[4];
    const float* dw1 = (const float*)d_in[5];
    const float* db1 = (const float*)d_in[6];
    const float* dw2 = (const float*)d_in[7];
    const float* db2 = (const float*)d_in[8];
    const float* dw3 = (const float*)d_in[9];
    const float* db3 = (const float*)d_in[10];
    const float* pw0 = (const float*)d_in[11];
    const float* pb0 = (const float*)d_in[12];
    const float* pw1 = (const float*)d_in[13];
    const float* pb1 = (const float*)d_in[14];
    const float* pw2 = (const float*)d_in[15];
    const float* pb2 = (const float*)d_in[16];
    float* out = (float*)d_out;

    cudaFuncSetAttribute(inter_gemm_kernel,
                         cudaFuncAttributeMaxDynamicSharedMemorySize,
                         GEMM_SMEM_FLOATS * (int)sizeof(float));

    dense_mlp_kernel<<<128, 256>>>(x, dw0, db0, dw1, db1, dw2, db2, dw3, db3);
    embed_kernel<<<52, 256>>>(sp, emb);
    inter_gemm_kernel<<<dim3(4, 4, 9), 256, GEMM_SMEM_FLOATS * sizeof(float)>>>(pw0);
    reduce_relu_kernel<<<512, 256>>>(pb0);
    pred_kernel<<<128, 256>>>(pw1, pb1, pw2, pb2, out);
}

// round 5
// speedup vs baseline: 1.1620x; 1.1620x over previous
#include <cuda_runtime.h>
#include <cuda_bf16.h>
#include <math.h>
#include <stdint.h>

// ---------------- scratch (device globals; no allocs allowed) ----------------
__device__ float g_z[512 * 448];           // z padded to 448 cols (cols 432..447 = 0)
__device__ float g_part[9 * 512 * 512];    // split-K partials
__device__ float g_h1[512 * 512];          // relu(inter@pw0+pb0)

// pack two fp32 -> bf16x2 (lo = first arg, hi = second arg)
__device__ __forceinline__ uint32_t pack_bf16(float lo, float hi) {
    uint32_t r;
    asm("cvt.rn.bf16x2.f32 %0, %1, %2;" : "=r"(r) : "f"(hi), "f"(lo));
    return r;
}

// ---------------- kernel 1: dense MLP (4 batch rows / block) ----------------
__global__ void dense_mlp_kernel(const float* __restrict__ x,
                                 const float* __restrict__ dw0, const float* __restrict__ db0,
                                 const float* __restrict__ dw1, const float* __restrict__ db1,
                                 const float* __restrict__ dw2, const float* __restrict__ db2,
                                 const float* __restrict__ dw3, const float* __restrict__ db3) {
    __shared__ float xs[4][13];
    __shared__ float h0[4][512];
    __shared__ float h1[4][256];
    __shared__ float h2[4][64];
    const int r0 = blockIdx.x * 4;
    const int tid = threadIdx.x;

    if (tid < 52) xs[tid / 13][tid % 13] = x[(r0 + tid / 13) * 13 + tid % 13];
    __syncthreads();

    #pragma unroll
    for (int jj = 0; jj < 2; jj++) {
        int j = tid + jj * 256;
        float a[4];
        float b = db0[j];
        #pragma unroll
        for (int r = 0; r < 4; r++) a[r] = b;
        #pragma unroll
        for (int i = 0; i < 13; i++) {
            float w = dw0[i * 512 + j];
            #pragma unroll
            for (int r = 0; r < 4; r++) a[r] += xs[r][i] * w;
        }
        #pragma unroll
        for (int r = 0; r < 4; r++) h0[r][j] = fmaxf(a[r], 0.f);
    }
    __syncthreads();

    {
        float a[4];
        float b = db1[tid];
        #pragma unroll
        for (int r = 0; r < 4; r++) a[r] = b;
        #pragma unroll 8
        for (int i = 0; i < 512; i++) {
            float w = dw1[i * 256 + tid];
            #pragma unroll
            for (int r = 0; r < 4; r++) a[r] += h0[r][i] * w;
        }
        #pragma unroll
        for (int r = 0; r < 4; r++) h1[r][tid] = fmaxf(a[r], 0.f);
    }
    __syncthreads();

    if (tid < 64) {
        float a[4];
        float b = db2[tid];
        #pragma unroll
        for (int r = 0; r < 4; r++) a[r] = b;
        #pragma unroll 8
        for (int i = 0; i < 256; i++) {
            float w = dw2[i * 64 + tid];
            #pragma unroll
            for (int r = 0; r < 4; r++) a[r] += h1[r][i] * w;
        }
        #pragma unroll
        for (int r = 0; r < 4; r++) h2[r][tid] = fmaxf(a[r], 0.f);
    }
    __syncthreads();

    if (tid < 16) {
        float a[4];
        float b = db3[tid];
        #pragma unroll
        for (int r = 0; r < 4; r++) a[r] = b;
        #pragma unroll
        for (int i = 0; i < 64; i++) {
            float w = dw3[i * 16 + tid];
            #pragma unroll
            for (int r = 0; r < 4; r++) a[r] += h2[r][i] * w;
        }
        #pragma unroll
        for (int r = 0; r < 4; r++) g_z[(size_t)(r0 + r) * 448 + tid] = a[r];
    }
    if (tid >= 64 && tid < 128) {
        int u = tid - 64;
        g_z[(size_t)(r0 + u / 16) * 448 + 432 + (u % 16)] = 0.f;
    }
}

// ---------------- kernel 2: embedding gather -> z[:,16:432] ----------------
__global__ void embed_kernel(const void* __restrict__ sp, const float* __restrict__ emb) {
    int t = blockIdx.x * blockDim.x + threadIdx.x;
    if (t >= 512 * 26) return;
    const int* si = (const int*)sp;
    bool is64 = (si[1] == 0 && si[3] == 0 && si[5] == 0);
    long long v = is64 ? ((const long long*)sp)[t] : (long long)si[t];
    int id = (int)((v + 1) % 100000);
    int b = t / 26, f = t - b * 26;
    const float4* src = (const float4*)(emb + ((size_t)f * 100000 + id) * 16);
    float4* dst = (float4*)(g_z + (size_t)b * 448 + 16 + f * 16);
    dst[0] = src[0]; dst[1] = src[1]; dst[2] = src[2]; dst[3] = src[3];
}

// ---------------- kernel 3: interaction GEMM (bf16 mma.sync), split-K ------
// C[512,512] = A[512,K] @ W0[K,512], A[b, p*432+q] = z[b,p]*z[b,q]
// per CTA: 128x128 tile, 48 p's (one split), q padded to 448 (14 chunks of 32)
// bf16 m16n8k16: 2 k-steps of 16 per 32-k iteration -> 32 HMMA/warp/iter.
#define GEMM_SMEM_FLOATS (128 * 33 + 128 * 49 + 2 * 32 * 132)

__global__ __launch_bounds__(256) void inter_gemm_kernel(const float* __restrict__ W0) {
    extern __shared__ float sm[];
    float* zq_s = sm;                        // [128][33]
    float* zp_s = sm + 128 * 33;             // [128][49]
    float* B_sm = sm + 128 * 33 + 128 * 49;  // [2][32][132]

    const int tid = threadIdx.x;
    const int warp = tid >> 5, lane = tid & 31;
    const int g = lane >> 2, c = lane & 3;             // mma group / thread-in-group
    const int m0 = blockIdx.x * 128;                   // m fastest: L2 dedupe of W0 stream
    const int n0 = blockIdx.y * 128;
    const int p0 = blockIdx.z * 48;
    const int wm0 = (warp >> 2) * 64, wn0 = (warp & 3) * 32;
    const int bk = tid >> 3;        // B stage: row (k) 0..31
    const int c8 = tid & 7;         // B stage: float4 col group

    // stage zp (this split's 48 p-columns of z)
    for (int i = tid; i < 128 * 48; i += 256) {
        int b = i / 48, j = i - b * 48;
        zp_s[b * 49 + j] = g_z[(size_t)(m0 + b) * 448 + p0 + j];
    }

    float acc[4][4][4];
    #pragma unroll
    for (int mi = 0; mi < 4; mi++)
        #pragma unroll
        for (int nj = 0; nj < 4; nj++)
            #pragma unroll
            for (int k = 0; k < 4; k++) acc[mi][nj][k] = 0.f;

    float4 breg[4];
#define LOAD_B(IT) {                                                        \
        int qq = (IT) / 48, pp = (IT) - qq * 48;                            \
        long long gk = (long long)(p0 + pp) * 432 + qq * 32 + bk;           \
        if (gk > 186623LL) gk = 186623LL;  /* padded q>=432: A==0 there */  \
        const float4* s4 = (const float4*)(W0 + gk * 512 + n0);             \
        breg[0] = s4[c8]; breg[1] = s4[c8 + 8];                             \
        breg[2] = s4[c8 + 16]; breg[3] = s4[c8 + 24]; }

    LOAD_B(0);
    // zq_r[j][u]: row (wm0 + g + 8j), k = 2c + (u&1) + 8*(u>>1)  (u = 0..7)
    float zq_r[8][8];
    float zp_r[8];

    for (int it = 0; it < 672; ++it) {             // 14 q-chunks * 48 p
        int qc = it / 48, pi = it - qc * 48;
        if (pi == 0) {
            __syncthreads();
            for (int i = tid; i < 128 * 32; i += 256) {
                int b = i >> 5, kk = i & 31;
                zq_s[b * 33 + kk] = g_z[(size_t)(m0 + b) * 448 + qc * 32 + kk];
            }
            __syncthreads();
            #pragma unroll
            for (int j = 0; j < 8; j++)
                #pragma unroll
                for (int u = 0; u < 8; u++)
                    zq_r[j][u] = zq_s[(wm0 + g + 8 * j) * 33 + 2 * c + (u & 1) + 8 * (u >> 1)];
        }
        // commit prefetched B tile to smem (raw fp32; bf16 rounding at frag pack)
        float* bb = B_sm + (it & 1) * (32 * 132);
        #pragma unroll
        for (int i = 0; i < 4; i++)
            *(float4*)(bb + bk * 132 + (c8 + 8 * i) * 4) = breg[i];
        __syncthreads();
        if (it + 1 < 672) LOAD_B(it + 1);  // prefetch next; latency hidden by MMA

        #pragma unroll
        for (int j = 0; j < 8; j++) zp_r[j] = zp_s[(wm0 + g + 8 * j) * 49 + pi];

        #pragma unroll
        for (int ks = 0; ks < 2; ks++) {           // two k16 steps
            // B fragments: [k][n] smem, rows 132 words (conflict-free: bank = 8c+g)
            uint32_t bu[4][2];
            #pragma unroll
            for (int nj = 0; nj < 4; nj++) {
                int nn = wn0 + nj * 8 + g;
                int kb = ks * 16 + 2 * c;
                bu[nj][0] = pack_bf16(bb[kb * 132 + nn],       bb[(kb + 1) * 132 + nn]);
                bu[nj][1] = pack_bf16(bb[(kb + 8) * 132 + nn], bb[(kb + 9) * 132 + nn]);
            }
            #pragma unroll
            for (int mi = 0; mi < 4; mi++) {
                float plo = zp_r[2 * mi], phi = zp_r[2 * mi + 1];
                uint32_t a0 = pack_bf16(plo * zq_r[2 * mi][4 * ks],         plo * zq_r[2 * mi][4 * ks + 1]);
                uint32_t a1 = pack_bf16(phi * zq_r[2 * mi + 1][4 * ks],     phi * zq_r[2 * mi + 1][4 * ks + 1]);
                uint32_t a2 = pack_bf16(plo * zq_r[2 * mi][4 * ks + 2],     plo * zq_r[2 * mi][4 * ks + 3]);
                uint32_t a3 = pack_bf16(phi * zq_r[2 * mi + 1][4 * ks + 2], phi * zq_r[2 * mi + 1][4 * ks + 3]);
                #pragma unroll
                for (int nj = 0; nj < 4; nj++) {
                    asm volatile(
                        "mma.sync.aligned.m16n8k16.row.col.f32.bf16.bf16.f32 "
                        "{%0,%1,%2,%3},{%4,%5,%6,%7},{%8,%9},{%0,%1,%2,%3};"
                        : "+f"(acc[mi][nj][0]), "+f"(acc[mi][nj][1]),
                          "+f"(acc[mi][nj][2]), "+f"(acc[mi][nj][3])
                        : "r"(a0), "r"(a1), "r"(a2), "r"(a3),
                          "r"(bu[nj][0]), "r"(bu[nj][1]));
                }
            }
        }
    }

    // epilogue: write split partials
    #pragma unroll
    for (int mi = 0; mi < 4; mi++)
        #pragma unroll
        for (int nj = 0; nj < 4; nj++) {
            int row = m0 + wm0 + 16 * mi + g;
            int col = n0 + wn0 + 8 * nj + 2 * c;
            float* d0 = g_part + ((size_t)blockIdx.z * 512 + row) * 512 + col;
            float* d1 = g_part + ((size_t)blockIdx.z * 512 + row + 8) * 512 + col;
            *(float2*)d0 = make_float2(acc[mi][nj][0], acc[mi][nj][1]);
            *(float2*)d1 = make_float2(acc[mi][nj][2], acc[mi][nj][3]);
        }
}
#undef LOAD_B

// ---------------- kernel 4: reduce split-K partials + bias + relu ----------
__global__ void reduce_relu_kernel(const float* __restrict__ pb0) {
    int b = blockIdx.x;
    for (int j = threadIdx.x; j < 512; j += 256) {
        float s = pb0[j];
        #pragma unroll
        for (int sp = 0; sp < 9; sp++)
            s += g_part[((size_t)sp * 512 + b) * 512 + j];
        g_h1[(size_t)b * 512 + j] = fmaxf(s, 0.f);
    }
}

// ---------------- kernel 5: prediction MLP + sigmoid -----------------------
__global__ void pred_kernel(const float* __restrict__ pw1, const float* __restrict__ pb1,
                            const float* __restrict__ pw2, const float* __restrict__ pb2,
                            float* __restrict__ out) {
    __shared__ float h1s[4][512];
    __shared__ float h2s[4][256];
    __shared__ float red[4][8];
    const int r0 = blockIdx.x * 4;
    const int tid = threadIdx.x;

    for (int i = tid; i < 2048; i += 256)
        h1s[i >> 9][i & 511] = g_h1[(size_t)(r0 + (i >> 9)) * 512 + (i & 511)];
    __syncthreads();

    {
        float a[4];
        float b = pb1[tid];
        #pragma unroll
        for (int r = 0; r < 4; r++) a[r] = b;
        #pragma unroll 8
        for (int i = 0; i < 512; i++) {
            float w = pw1[i * 256 + tid];
            #pragma unroll
            for (int r = 0; r < 4; r++) a[r] += h1s[r][i] * w;
        }
        #pragma unroll
        for (int r = 0; r < 4; r++) h2s[r][tid] = fmaxf(a[r], 0.f);
    }
    __syncthreads();

    float w2 = pw2[tid];
    int lane = tid & 31, wp = tid >> 5;
    #pragma unroll
    for (int r = 0; r < 4; r++) {
        float v = h2s[r][tid] * w2;
        #pragma unroll
        for (int o = 16; o; o >>= 1) v += __shfl_xor_sync(0xffffffffu, v, o);
        if (lane == 0) red[r][wp] = v;
    }
    __syncthreads();
    if (tid < 4) {
        float s = pb2[0];
        #pragma unroll
        for (int w = 0; w < 8; w++) s += red[tid][w];
        out[r0 + tid] = 1.f / (1.f + expf(-s));
    }
}

// ---------------- launch ----------------------------------------------------
extern "C" void kernel_launch(void* const* d_in, const int* in_sizes, int n_in,
                              void* d_out, int out_size) {
    const float* x   = (const float*)d_in[0];
    const void*  sp  = d_in[1];
    const float* emb = (const float*)d_in[2];
    const float* dw0 = (const float*)d_in[3];
    const float* db0 = (const float*)d_in[4];
    const float* dw1 = (const float*)d_in[5];
    const float* db1 = (const float*)d_in[6];
    const float* dw2 = (const float*)d_in[7];
    const float* db2 = (const float*)d_in[8];
    const float* dw3 = (const float*)d_in[9];
    const float* db3 = (const float*)d_in[10];
    const float* pw0 = (const float*)d_in[11];
    const float* pb0 = (const float*)d_in[12];
    const float* pw1 = (const float*)d_in[13];
    const float* pb1 = (const float*)d_in[14];
    const float* pw2 = (const float*)d_in[15];
    const float* pb2 = (const float*)d_in[16];
    float* out = (float*)d_out;

    cudaFuncSetAttribute(inter_gemm_kernel,
                         cudaFuncAttributeMaxDynamicSharedMemorySize,
                         GEMM_SMEM_FLOATS * (int)sizeof(float));

    dense_mlp_kernel<<<128, 256>>>(x, dw0, db0, dw1, db1, dw2, db2, dw3, db3);
    embed_kernel<<<52, 256>>>(sp, emb);
    inter_gemm_kernel<<<dim3(4, 4, 9), 256, GEMM_SMEM_FLOATS * sizeof(float)>>>(pw0);
    reduce_relu_kernel<<<512, 256>>>(pb0);
    pred_kernel<<<128, 256>>>(pw1, pb1, pw2, pb2, out);
}